// round 2
// baseline (speedup 1.0000x reference)
#include <cuda_runtime.h>
#include <cuda_fp16.h>
#include <math.h>

#define BATCH 4
#define CH    256
#define HH    100
#define WW    100
#define HWTOT (HH * WW)

// Scratch: x transposed to [B, H, W, C] in fp16. 4*10000*256*2 = 20.48 MB.
__device__ __half g_xt[(size_t)BATCH * HWTOT * CH];

// ---------------------------------------------------------------------------
// Kernel 1: [B,C,H,W] f32 -> [B,HW,C] fp16 via smem-tiled transpose.
// grid: (ceil(HW/32), C/32, B), block: (32, 8)
// ---------------------------------------------------------------------------
__global__ void transpose_f32_to_f16(const float* __restrict__ x) {
    __shared__ float tile[32][33];
    int b  = blockIdx.z;
    int c0 = blockIdx.y * 32;
    int s0 = blockIdx.x * 32;
    int tx = threadIdx.x, ty = threadIdx.y;
    const float* xb = x + (size_t)b * CH * HWTOT;
#pragma unroll
    for (int i = 0; i < 32; i += 8) {
        int s = s0 + tx;
        if (s < HWTOT)
            tile[ty + i][tx] = xb[(size_t)(c0 + ty + i) * HWTOT + s];
    }
    __syncthreads();
    __half* xtb = g_xt + (size_t)b * HWTOT * CH;
#pragma unroll
    for (int i = 0; i < 32; i += 8) {
        int s = s0 + ty + i;
        if (s < HWTOT)
            xtb[(size_t)s * CH + c0 + tx] = __float2half_rn(tile[tx][ty + i]);
    }
}

// ---------------------------------------------------------------------------
// Kernel 2: 4 pixels per warp (8 lanes/pixel, 32 channels/lane).
// Per corner: 4x LDG.128 (32 halves) + 16 HFMA2. All accumulation in fp16.
// ---------------------------------------------------------------------------
__device__ __forceinline__ void corner_acc_h2(__half2 samp[16], const __half* ptr,
                                              __half2 wgt) {
    const uint4* q = (const uint4*)ptr;
    uint4 u0 = __ldg(q + 0);
    uint4 u1 = __ldg(q + 1);
    uint4 u2 = __ldg(q + 2);
    uint4 u3 = __ldg(q + 3);
    const unsigned* uu = (const unsigned*)&u0;  // 16 consecutive words (u0..u3)
#pragma unroll
    for (int i = 0; i < 4; i++) {
        samp[i +  0] = __hfma2(wgt, *(const __half2*)(&u0.x + i), samp[i +  0]);
        samp[i +  4] = __hfma2(wgt, *(const __half2*)(&u1.x + i), samp[i +  4]);
        samp[i +  8] = __hfma2(wgt, *(const __half2*)(&u2.x + i), samp[i +  8]);
        samp[i + 12] = __hfma2(wgt, *(const __half2*)(&u3.x + i), samp[i + 12]);
    }
    (void)uu;
}

__global__ __launch_bounds__(256, 2) void dsa_main(
    const float* __restrict__ offset, const float* __restrict__ w0,
    const float* __restrict__ b0, float* __restrict__ out)
{
    int warpId = threadIdx.x >> 5;
    int lane   = threadIdx.x & 31;
    int sub    = lane & 7;    // channel group within pixel, 0..7
    int pix    = lane >> 3;   // pixel within warp, 0..3

    int p  = (blockIdx.x * 8 + warpId) * 4 + pix;   // pixel id, 0..39999
    int b  = p / HWTOT;
    int hw = p - b * HWTOT;
    int h  = hw / WW;
    int w  = hw - h * WW;
    int c0 = sub * 32;

    const __half* xb   = g_xt + (size_t)b * HWTOT * CH + c0;
    const float*  offb = offset + (size_t)b * 18 * HWTOT + hw;

    __half2 feat[16];
    __half2 ninf = __float2half2_rn(-65504.f);
#pragma unroll
    for (int j = 0; j < 16; j++) feat[j] = ninf;

#pragma unroll
    for (int k = 0; k < 9; k++) {
        float offy = __ldg(offb + (2 * k) * HWTOT);
        float offx = __ldg(offb + (2 * k + 1) * HWTOT);
        float py = (float)(h + (k / 3) - 1) + offy;
        float px = (float)(w + (k % 3) - 1) + offx;
        float y0f = floorf(py), x0f = floorf(px);
        float wy = py - y0f, wx = px - x0f;
        int y0 = (int)y0f, x0 = (int)x0f;
        int y1 = y0 + 1,   x1 = x0 + 1;
        bool vy0 = (unsigned)y0 < (unsigned)HH;
        bool vy1 = (unsigned)y1 < (unsigned)HH;
        bool vx0 = (unsigned)x0 < (unsigned)WW;
        bool vx1 = (unsigned)x1 < (unsigned)WW;
        float f00 = (1.f - wy) * (1.f - wx); if (!(vy0 && vx0)) f00 = 0.f;
        float f01 = (1.f - wy) * wx;         if (!(vy0 && vx1)) f01 = 0.f;
        float f10 = wy * (1.f - wx);         if (!(vy1 && vx0)) f10 = 0.f;
        float f11 = wy * wx;                 if (!(vy1 && vx1)) f11 = 0.f;
        int yc0 = min(max(y0, 0), HH - 1), yc1 = min(max(y1, 0), HH - 1);
        int xc0 = min(max(x0, 0), WW - 1), xc1 = min(max(x1, 0), WW - 1);

        __half2 samp[16];
#pragma unroll
        for (int j = 0; j < 16; j++) samp[j] = __float2half2_rn(0.f);

        corner_acc_h2(samp, xb + (size_t)(yc0 * WW + xc0) * CH, __float2half2_rn(f00));
        corner_acc_h2(samp, xb + (size_t)(yc0 * WW + xc1) * CH, __float2half2_rn(f01));
        corner_acc_h2(samp, xb + (size_t)(yc1 * WW + xc0) * CH, __float2half2_rn(f10));
        corner_acc_h2(samp, xb + (size_t)(yc1 * WW + xc1) * CH, __float2half2_rn(f11));
#pragma unroll
        for (int j = 0; j < 16; j++) feat[j] = __hmax2(feat[j], samp[j]);
    }

    // Dot with w0 over this lane's 32 channels (f32), then reduce over 8 lanes.
    float acc = 0.f;
#pragma unroll
    for (int i = 0; i < 8; i++) {
        float4 wv = __ldg((const float4*)(w0 + c0 + i * 4));
        float2 f0 = __half22float2(feat[2 * i]);
        float2 f1 = __half22float2(feat[2 * i + 1]);
        acc += wv.x * f0.x + wv.y * f0.y + wv.z * f1.x + wv.w * f1.y;
    }
#pragma unroll
    for (int s = 4; s > 0; s >>= 1)
        acc += __shfl_xor_sync(0xffffffffu, acc, s);
    if (sub == 0) {
        float v = acc + __ldg(b0);
        out[p] = 1.f / (1.f + expf(-v));
    }
}

// ---------------------------------------------------------------------------
extern "C" void kernel_launch(void* const* d_in, const int* in_sizes, int n_in,
                              void* d_out, int out_size)
{
    const float *x = nullptr, *offset = nullptr, *w0 = nullptr, *b0 = nullptr;
    for (int i = 0; i < n_in; i++) {
        if      (in_sizes[i] == BATCH * CH * HWTOT) x      = (const float*)d_in[i];
        else if (in_sizes[i] == BATCH * 18 * HWTOT) offset = (const float*)d_in[i];
        else if (in_sizes[i] == CH)                 w0     = (const float*)d_in[i];
        else if (in_sizes[i] == 1)                  b0     = (const float*)d_in[i];
    }

    dim3 tb(32, 8);
    dim3 tg((HWTOT + 31) / 32, CH / 32, BATCH);
    transpose_f32_to_f16<<<tg, tb>>>(x);

    // 4 pixels per warp, 8 warps per block -> 32 pixels per block.
    dsa_main<<<(BATCH * HWTOT) / 32, 256>>>(offset, w0, b0, (float*)d_out);
}

// round 3
// speedup vs baseline: 2.1999x; 2.1999x over previous
#include <cuda_runtime.h>
#include <cuda_fp16.h>
#include <math.h>

#define BATCH 4
#define CH    256
#define HH    100
#define WW    100
#define HWTOT (HH * WW)
#define NPIX  (BATCH * HWTOT)

// Scratch: x transposed to [B, H, W, C] in fp16. 20.48 MB.
__device__ __half g_xt[(size_t)NPIX * CH];
// Per-(tap, pixel) metadata: {half2 w00w01, half2 w10w11, u16 idx x4}. 5.76 MB.
__device__ uint4  g_meta[9 * NPIX];

// ---------------------------------------------------------------------------
// Kernel 1: [B,C,H,W] f32 -> [B,HW,C] fp16 via smem-tiled transpose.
// ---------------------------------------------------------------------------
__global__ void transpose_f32_to_f16(const float* __restrict__ x) {
    __shared__ float tile[32][33];
    int b  = blockIdx.z;
    int c0 = blockIdx.y * 32;
    int s0 = blockIdx.x * 32;
    int tx = threadIdx.x, ty = threadIdx.y;
    const float* xb = x + (size_t)b * CH * HWTOT;
#pragma unroll
    for (int i = 0; i < 32; i += 8) {
        int s = s0 + tx;
        if (s < HWTOT)
            tile[ty + i][tx] = xb[(size_t)(c0 + ty + i) * HWTOT + s];
    }
    __syncthreads();
    __half* xtb = g_xt + (size_t)b * HWTOT * CH;
#pragma unroll
    for (int i = 0; i < 32; i += 8) {
        int s = s0 + ty + i;
        if (s < HWTOT)
            xtb[(size_t)s * CH + c0 + tx] = __float2half_rn(tile[tx][ty + i]);
    }
}

// ---------------------------------------------------------------------------
// Kernel 2: per-(tap,pixel) bilinear weights + clamped corner indices.
// t = k*NPIX + b*HWTOT + hw  (coalesced offset reads and meta writes)
// ---------------------------------------------------------------------------
__global__ __launch_bounds__(256) void precompute_meta(const float* __restrict__ offset) {
    int t = blockIdx.x * 256 + threadIdx.x;
    if (t >= 9 * NPIX) return;
    int k  = t / NPIX;
    int r  = t - k * NPIX;
    int b  = r / HWTOT;
    int hw = r - b * HWTOT;
    int h  = hw / WW;
    int w  = hw - h * WW;

    float offy = offset[(size_t)(b * 18 + 2 * k) * HWTOT + hw];
    float offx = offset[(size_t)(b * 18 + 2 * k + 1) * HWTOT + hw];
    float py = (float)(h + k / 3 - 1) + offy;
    float px = (float)(w + k % 3 - 1) + offx;
    float y0f = floorf(py), x0f = floorf(px);
    float wy = py - y0f, wx = px - x0f;
    int y0 = (int)y0f, x0 = (int)x0f;
    int y1 = y0 + 1,   x1 = x0 + 1;
    bool vy0 = (unsigned)y0 < (unsigned)HH;
    bool vy1 = (unsigned)y1 < (unsigned)HH;
    bool vx0 = (unsigned)x0 < (unsigned)WW;
    bool vx1 = (unsigned)x1 < (unsigned)WW;
    float f00 = (1.f - wy) * (1.f - wx); if (!(vy0 && vx0)) f00 = 0.f;
    float f01 = (1.f - wy) * wx;         if (!(vy0 && vx1)) f01 = 0.f;
    float f10 = wy * (1.f - wx);         if (!(vy1 && vx0)) f10 = 0.f;
    float f11 = wy * wx;                 if (!(vy1 && vx1)) f11 = 0.f;
    int yc0 = min(max(y0, 0), HH - 1), yc1 = min(max(y1, 0), HH - 1);
    int xc0 = min(max(x0, 0), WW - 1), xc1 = min(max(x1, 0), WW - 1);

    __half2 wA = __floats2half2_rn(f00, f01);
    __half2 wB = __floats2half2_rn(f10, f11);
    uint4 m;
    m.x = *(const unsigned*)&wA;
    m.y = *(const unsigned*)&wB;
    m.z = (unsigned)(yc0 * WW + xc0) | ((unsigned)(yc0 * WW + xc1) << 16);
    m.w = (unsigned)(yc1 * WW + xc0) | ((unsigned)(yc1 * WW + xc1) << 16);
    g_meta[t] = m;
}

// ---------------------------------------------------------------------------
// Kernel 3: warp-per-pixel gather + max + dot + sigmoid. Lane = 8 channels.
// Per corner: 1 LDG.128 (8 halves) + 4 HFMA2. Tiny register footprint.
// ---------------------------------------------------------------------------
__device__ __forceinline__ void corner8(__half2 s[4], const __half* p, __half2 w) {
    uint4 u = __ldg((const uint4*)p);
    s[0] = __hfma2(w, *(const __half2*)&u.x, s[0]);
    s[1] = __hfma2(w, *(const __half2*)&u.y, s[1]);
    s[2] = __hfma2(w, *(const __half2*)&u.z, s[2]);
    s[3] = __hfma2(w, *(const __half2*)&u.w, s[3]);
}

__global__ __launch_bounds__(256) void dsa_main(
    const float* __restrict__ w0, const float* __restrict__ b0,
    float* __restrict__ out)
{
    int warpId = threadIdx.x >> 5;
    int lane   = threadIdx.x & 31;
    int p  = blockIdx.x * 8 + warpId;    // pixel id, 0..NPIX-1
    int b  = p / HWTOT;
    int c0 = lane * 8;

    const __half* xb = g_xt + (size_t)b * HWTOT * CH + c0;

    __half2 feat[4];
    __half2 ninf = __float2half2_rn(-65504.f);
#pragma unroll
    for (int j = 0; j < 4; j++) feat[j] = ninf;

#pragma unroll
    for (int k = 0; k < 9; k++) {
        uint4 m = __ldg(&g_meta[k * NPIX + p]);   // warp-broadcast 16B
        __half2 wA = *(const __half2*)&m.x;        // (w00, w01)
        __half2 wB = *(const __half2*)&m.y;        // (w10, w11)
        unsigned i00 = m.z & 0xFFFFu, i01 = m.z >> 16;
        unsigned i10 = m.w & 0xFFFFu, i11 = m.w >> 16;

        __half2 samp[4];
        __half2 z = __float2half2_rn(0.f);
#pragma unroll
        for (int j = 0; j < 4; j++) samp[j] = z;

        corner8(samp, xb + (size_t)i00 * CH, __low2half2(wA));
        corner8(samp, xb + (size_t)i01 * CH, __high2half2(wA));
        corner8(samp, xb + (size_t)i10 * CH, __low2half2(wB));
        corner8(samp, xb + (size_t)i11 * CH, __high2half2(wB));
#pragma unroll
        for (int j = 0; j < 4; j++) feat[j] = __hmax2(feat[j], samp[j]);
    }

    // Dot with w0 over this lane's 8 channels (f32), reduce across 32 lanes.
    float4 wa = __ldg((const float4*)(w0 + c0));
    float4 wb = __ldg((const float4*)(w0 + c0 + 4));
    float2 f0 = __half22float2(feat[0]);
    float2 f1 = __half22float2(feat[1]);
    float2 f2 = __half22float2(feat[2]);
    float2 f3 = __half22float2(feat[3]);
    float acc = wa.x * f0.x + wa.y * f0.y + wa.z * f1.x + wa.w * f1.y
              + wb.x * f2.x + wb.y * f2.y + wb.z * f3.x + wb.w * f3.y;
#pragma unroll
    for (int s = 16; s > 0; s >>= 1)
        acc += __shfl_xor_sync(0xffffffffu, acc, s);
    if (lane == 0) {
        float v = acc + __ldg(b0);
        out[p] = 1.f / (1.f + expf(-v));
    }
}

// ---------------------------------------------------------------------------
extern "C" void kernel_launch(void* const* d_in, const int* in_sizes, int n_in,
                              void* d_out, int out_size)
{
    const float *x = nullptr, *offset = nullptr, *w0 = nullptr, *b0 = nullptr;
    for (int i = 0; i < n_in; i++) {
        if      (in_sizes[i] == BATCH * CH * HWTOT) x      = (const float*)d_in[i];
        else if (in_sizes[i] == BATCH * 18 * HWTOT) offset = (const float*)d_in[i];
        else if (in_sizes[i] == CH)                 w0     = (const float*)d_in[i];
        else if (in_sizes[i] == 1)                  b0     = (const float*)d_in[i];
    }

    dim3 tb(32, 8);
    dim3 tg((HWTOT + 31) / 32, CH / 32, BATCH);
    transpose_f32_to_f16<<<tg, tb>>>(x);

    precompute_meta<<<(9 * NPIX + 255) / 256, 256>>>(offset);

    dsa_main<<<NPIX / 8, 256>>>(w0, b0, (float*)d_out);
}

// round 5
// speedup vs baseline: 2.2664x; 1.0302x over previous
#include <cuda_runtime.h>
#include <cuda_fp16.h>
#include <math.h>

#define BATCH 4
#define CH    256
#define HH    100
#define WW    100
#define HWTOT (HH * WW)
#define NPIX  (BATCH * HWTOT)

// Scratch: x transposed to [B, H, W, C] in fp16. 20.48 MB.
__device__ __half g_xt[(size_t)NPIX * CH];
// Per-(tap, pixel) metadata: {half2 w00w01, half2 w10w11, u16 idx x4}. 5.76 MB.
__device__ uint4  g_meta[9 * NPIX];

// ---------------------------------------------------------------------------
// Kernel 1: [B,C,H,W] f32 -> [B,HW,C] fp16.
// Tile: 64 channels x 64 spatial. Load float2 (LDG.64), convert to fp16 at
// load into half2-keyed smem; write one half2 (STG.32) per lane, fully
// coalesced 128B per warp, conflict-free LDS.
// grid: (ceil(HW/64), C/64, B), block: (32, 8)
// ---------------------------------------------------------------------------
__global__ __launch_bounds__(256) void transpose_f32_to_f16(const float* __restrict__ x) {
    // tile[j][s] = channels (2j, 2j+1) at spatial s (within tile)
    __shared__ __half2 tile[32][65];
    int b  = blockIdx.z;
    int c0 = blockIdx.y * 64;
    int s0 = blockIdx.x * 64;
    int tx = threadIdx.x, ty = threadIdx.y;
    const float* xb = x + (size_t)b * CH * HWTOT;

    int s = s0 + 2 * tx;
#pragma unroll
    for (int i = 0; i < 8; i++) {
        int row = ty + 8 * i;              // channel within tile, 0..63
        if (s < HWTOT) {
            float2 v = *(const float2*)(xb + (size_t)(c0 + row) * HWTOT + s);
            __half* hp = (__half*)&tile[row >> 1][2 * tx] + (row & 1);
            hp[0] = __float2half_rn(v.x);
            hp[2] = __float2half_rn(v.y);
        }
    }
    __syncthreads();

    __half* xtb = g_xt + (size_t)b * HWTOT * CH;
#pragma unroll
    for (int it = 0; it < 8; it++) {
        int sl = ty * 8 + it;              // spatial within tile, 0..63
        int ss = s0 + sl;
        if (ss < HWTOT)
            *(__half2*)(xtb + (size_t)ss * CH + c0 + 2 * tx) = tile[tx][sl];
    }
}

// ---------------------------------------------------------------------------
// Kernel 2: per-(tap,pixel) bilinear weights + clamped corner indices.
// t = k*NPIX + b*HWTOT + hw  (coalesced offset reads and meta writes)
// ---------------------------------------------------------------------------
__global__ __launch_bounds__(256) void precompute_meta(const float* __restrict__ offset) {
    int t = blockIdx.x * 256 + threadIdx.x;
    if (t >= 9 * NPIX) return;
    int k  = t / NPIX;
    int r  = t - k * NPIX;
    int b  = r / HWTOT;
    int hw = r - b * HWTOT;
    int h  = hw / WW;
    int w  = hw - h * WW;

    float offy = offset[(size_t)(b * 18 + 2 * k) * HWTOT + hw];
    float offx = offset[(size_t)(b * 18 + 2 * k + 1) * HWTOT + hw];
    float py = (float)(h + k / 3 - 1) + offy;
    float px = (float)(w + k % 3 - 1) + offx;
    float y0f = floorf(py), x0f = floorf(px);
    float wy = py - y0f, wx = px - x0f;
    int y0 = (int)y0f, x0 = (int)x0f;
    int y1 = y0 + 1,   x1 = x0 + 1;
    bool vy0 = (unsigned)y0 < (unsigned)HH;
    bool vy1 = (unsigned)y1 < (unsigned)HH;
    bool vx0 = (unsigned)x0 < (unsigned)WW;
    bool vx1 = (unsigned)x1 < (unsigned)WW;
    float f00 = (1.f - wy) * (1.f - wx); if (!(vy0 && vx0)) f00 = 0.f;
    float f01 = (1.f - wy) * wx;         if (!(vy0 && vx1)) f01 = 0.f;
    float f10 = wy * (1.f - wx);         if (!(vy1 && vx0)) f10 = 0.f;
    float f11 = wy * wx;                 if (!(vy1 && vx1)) f11 = 0.f;
    int yc0 = min(max(y0, 0), HH - 1), yc1 = min(max(y1, 0), HH - 1);
    int xc0 = min(max(x0, 0), WW - 1), xc1 = min(max(x1, 0), WW - 1);

    __half2 wA = __floats2half2_rn(f00, f01);
    __half2 wB = __floats2half2_rn(f10, f11);
    uint4 m;
    m.x = *(const unsigned*)&wA;
    m.y = *(const unsigned*)&wB;
    m.z = (unsigned)(yc0 * WW + xc0) | ((unsigned)(yc0 * WW + xc1) << 16);
    m.w = (unsigned)(yc1 * WW + xc0) | ((unsigned)(yc1 * WW + xc1) << 16);
    g_meta[t] = m;
}

// ---------------------------------------------------------------------------
// Kernel 3: warp-per-pixel gather + max + dot + sigmoid. Lane = 8 channels.
// Per corner: 1 LDG.128 (8 halves) + 4 HFMA2. 32-bit addressing.
// ---------------------------------------------------------------------------
__device__ __forceinline__ void corner8(__half2 s[4], const __half* base,
                                        unsigned byteOff, __half2 w) {
    uint4 u = __ldg((const uint4*)((const char*)base + byteOff));
    s[0] = __hfma2(w, *(const __half2*)&u.x, s[0]);
    s[1] = __hfma2(w, *(const __half2*)&u.y, s[1]);
    s[2] = __hfma2(w, *(const __half2*)&u.z, s[2]);
    s[3] = __hfma2(w, *(const __half2*)&u.w, s[3]);
}

__global__ __launch_bounds__(256) void dsa_main(
    const float* __restrict__ w0, const float* __restrict__ b0,
    float* __restrict__ out)
{
    int warpId = threadIdx.x >> 5;
    int lane   = threadIdx.x & 31;
    int p  = blockIdx.x * 8 + warpId;    // pixel id, 0..NPIX-1
    int b  = p / HWTOT;
    int c0 = lane * 8;

    const __half* xb = g_xt + (size_t)b * HWTOT * CH + c0;

    __half2 feat[4];
    __half2 ninf = __float2half2_rn(-65504.f);
#pragma unroll
    for (int j = 0; j < 4; j++) feat[j] = ninf;

#pragma unroll
    for (int k = 0; k < 9; k++) {
        uint4 m = __ldg(&g_meta[k * NPIX + p]);   // warp-broadcast 16B
        __half2 wA = *(const __half2*)&m.x;        // (w00, w01)
        __half2 wB = *(const __half2*)&m.y;        // (w10, w11)
        // corner byte offsets: idx * CH * sizeof(half) = idx << 9
        unsigned o00 = (m.z & 0xFFFFu) << 9, o01 = (m.z >> 16) << 9;
        unsigned o10 = (m.w & 0xFFFFu) << 9, o11 = (m.w >> 16) << 9;

        __half2 samp[4];
        __half2 z = __float2half2_rn(0.f);
#pragma unroll
        for (int j = 0; j < 4; j++) samp[j] = z;

        corner8(samp, xb, o00, __low2half2(wA));
        corner8(samp, xb, o01, __high2half2(wA));
        corner8(samp, xb, o10, __low2half2(wB));
        corner8(samp, xb, o11, __high2half2(wB));
#pragma unroll
        for (int j = 0; j < 4; j++) feat[j] = __hmax2(feat[j], samp[j]);
    }

    // Dot with w0 over this lane's 8 channels (f32), reduce across 32 lanes.
    float4 wa = __ldg((const float4*)(w0 + c0));
    float4 wb = __ldg((const float4*)(w0 + c0 + 4));
    float2 f0 = __half22float2(feat[0]);
    float2 f1 = __half22float2(feat[1]);
    float2 f2 = __half22float2(feat[2]);
    float2 f3 = __half22float2(feat[3]);
    float acc = wa.x * f0.x + wa.y * f0.y + wa.z * f1.x + wa.w * f1.y
              + wb.x * f2.x + wb.y * f2.y + wb.z * f3.x + wb.w * f3.y;
#pragma unroll
    for (int s = 16; s > 0; s >>= 1)
        acc += __shfl_xor_sync(0xffffffffu, acc, s);
    if (lane == 0) {
        float v = acc + __ldg(b0);
        out[p] = 1.f / (1.f + expf(-v));
    }
}

// ---------------------------------------------------------------------------
extern "C" void kernel_launch(void* const* d_in, const int* in_sizes, int n_in,
                              void* d_out, int out_size)
{
    const float *x = nullptr, *offset = nullptr, *w0 = nullptr, *b0 = nullptr;
    for (int i = 0; i < n_in; i++) {
        if      (in_sizes[i] == BATCH * CH * HWTOT) x      = (const float*)d_in[i];
        else if (in_sizes[i] == BATCH * 18 * HWTOT) offset = (const float*)d_in[i];
        else if (in_sizes[i] == CH)                 w0     = (const float*)d_in[i];
        else if (in_sizes[i] == 1)                  b0     = (const float*)d_in[i];
    }

    dim3 tb(32, 8);
    dim3 tg((HWTOT + 63) / 64, CH / 64, BATCH);
    transpose_f32_to_f16<<<tg, tb>>>(x);

    precompute_meta<<<(9 * NPIX + 255) / 256, 256>>>(offset);

    dsa_main<<<NPIX / 8, 256>>>(w0, b0, (float*)d_out);
}

// round 6
// speedup vs baseline: 2.4785x; 1.0936x over previous
#include <cuda_runtime.h>
#include <cuda_fp16.h>
#include <math.h>

#define BATCH 4
#define CH    256
#define HH    100
#define WW    100
#define HWTOT (HH * WW)
#define NPIX  (BATCH * HWTOT)

#define STILE 157                        // ceil(HWTOT/64)
#define MGRID ((9 * NPIX + 255) / 256)   // 1407 meta blocks
#define TGRID (STILE * (CH / 64) * BATCH) // 2512 transpose blocks

// Scratch: x transposed to [B, H, W, C] in fp16. 20.48 MB.
__device__ __half g_xt[(size_t)NPIX * CH];
// Per-(tap, pixel) metadata: {half2 w00w01, half2 w10w11, u16 idx x4}. 5.76 MB.
__device__ uint4  g_meta[9 * NPIX];

// ---------------------------------------------------------------------------
// Kernel 1 (fused): blocks [0, MGRID) do per-(tap,pixel) meta precompute;
// blocks [MGRID, MGRID+TGRID) do the [B,C,H,W] f32 -> [B,HW,C] fp16 transpose.
// Meta blocks are scheduled first so their ALU work hides in the transpose's
// DRAM stalls.
// ---------------------------------------------------------------------------
__global__ __launch_bounds__(256) void prep(const float* __restrict__ x,
                                            const float* __restrict__ offset)
{
    int bx = blockIdx.x;
    if (bx < MGRID) {
        // ---- meta precompute ----
        int t = bx * 256 + threadIdx.x;
        if (t >= 9 * NPIX) return;
        int k  = t / NPIX;
        int r  = t - k * NPIX;
        int b  = r / HWTOT;
        int hw = r - b * HWTOT;
        int h  = hw / WW;
        int w  = hw - h * WW;

        float offy = offset[(size_t)(b * 18 + 2 * k) * HWTOT + hw];
        float offx = offset[(size_t)(b * 18 + 2 * k + 1) * HWTOT + hw];
        float py = (float)(h + k / 3 - 1) + offy;
        float px = (float)(w + k % 3 - 1) + offx;
        float y0f = floorf(py), x0f = floorf(px);
        float wy = py - y0f, wx = px - x0f;
        int y0 = (int)y0f, x0 = (int)x0f;
        int y1 = y0 + 1,   x1 = x0 + 1;
        bool vy0 = (unsigned)y0 < (unsigned)HH;
        bool vy1 = (unsigned)y1 < (unsigned)HH;
        bool vx0 = (unsigned)x0 < (unsigned)WW;
        bool vx1 = (unsigned)x1 < (unsigned)WW;
        float f00 = (1.f - wy) * (1.f - wx); if (!(vy0 && vx0)) f00 = 0.f;
        float f01 = (1.f - wy) * wx;         if (!(vy0 && vx1)) f01 = 0.f;
        float f10 = wy * (1.f - wx);         if (!(vy1 && vx0)) f10 = 0.f;
        float f11 = wy * wx;                 if (!(vy1 && vx1)) f11 = 0.f;
        int yc0 = min(max(y0, 0), HH - 1), yc1 = min(max(y1, 0), HH - 1);
        int xc0 = min(max(x0, 0), WW - 1), xc1 = min(max(x1, 0), WW - 1);

        __half2 wA = __floats2half2_rn(f00, f01);
        __half2 wB = __floats2half2_rn(f10, f11);
        uint4 m;
        m.x = *(const unsigned*)&wA;
        m.y = *(const unsigned*)&wB;
        m.z = (unsigned)(yc0 * WW + xc0) | ((unsigned)(yc0 * WW + xc1) << 16);
        m.w = (unsigned)(yc1 * WW + xc0) | ((unsigned)(yc1 * WW + xc1) << 16);
        g_meta[t] = m;
    } else {
        // ---- transpose: 64ch x 64sp tile ----
        __shared__ __half2 tile[32][65];
        int tb   = bx - MGRID;
        int sx   = tb % STILE;
        int rest = tb / STILE;
        int cy   = rest & 3;          // CH/64 = 4
        int b    = rest >> 2;
        int c0 = cy * 64;
        int s0 = sx * 64;
        int tx = threadIdx.x & 31, ty = threadIdx.x >> 5;
        const float* xb = x + (size_t)b * CH * HWTOT;

        int s = s0 + 2 * tx;
#pragma unroll
        for (int i = 0; i < 8; i++) {
            int row = ty + 8 * i;              // channel within tile, 0..63
            if (s < HWTOT) {
                float2 v = *(const float2*)(xb + (size_t)(c0 + row) * HWTOT + s);
                __half* hp = (__half*)&tile[row >> 1][2 * tx] + (row & 1);
                hp[0] = __float2half_rn(v.x);
                hp[2] = __float2half_rn(v.y);
            }
        }
        __syncthreads();

        __half* xtb = g_xt + (size_t)b * HWTOT * CH;
#pragma unroll
        for (int it = 0; it < 8; it++) {
            int sl = ty * 8 + it;              // spatial within tile, 0..63
            int ss = s0 + sl;
            if (ss < HWTOT)
                *(__half2*)(xtb + (size_t)ss * CH + c0 + 2 * tx) = tile[tx][sl];
        }
    }
}

// ---------------------------------------------------------------------------
// Kernel 2: warp-per-pixel gather + max + dot + sigmoid. Lane = 8 channels.
// Per-block meta staged in smem (coalesced load, broadcast LDS in tap loop).
// ---------------------------------------------------------------------------
__device__ __forceinline__ void corner8_mul(__half2 s[4], const __half* base,
                                            unsigned byteOff, __half2 w) {
    uint4 u = __ldg((const uint4*)((const char*)base + byteOff));
    s[0] = __hmul2(w, *(const __half2*)&u.x);
    s[1] = __hmul2(w, *(const __half2*)&u.y);
    s[2] = __hmul2(w, *(const __half2*)&u.z);
    s[3] = __hmul2(w, *(const __half2*)&u.w);
}

__device__ __forceinline__ void corner8(__half2 s[4], const __half* base,
                                        unsigned byteOff, __half2 w) {
    uint4 u = __ldg((const uint4*)((const char*)base + byteOff));
    s[0] = __hfma2(w, *(const __half2*)&u.x, s[0]);
    s[1] = __hfma2(w, *(const __half2*)&u.y, s[1]);
    s[2] = __hfma2(w, *(const __half2*)&u.z, s[2]);
    s[3] = __hfma2(w, *(const __half2*)&u.w, s[3]);
}

__global__ __launch_bounds__(256) void dsa_main(
    const float* __restrict__ w0, const float* __restrict__ b0,
    float* __restrict__ out)
{
    __shared__ uint4 smeta[8][9];      // [warp/pixel][tap]
    int tid    = threadIdx.x;
    int warpId = tid >> 5;
    int lane   = tid & 31;
    int p0 = blockIdx.x * 8;

    // Cooperative stage: i = k*8 + wp -> 8 consecutive pixels = 128B coalesced.
    if (tid < 72) {
        int k = tid >> 3, wp = tid & 7;
        smeta[wp][k] = __ldg(&g_meta[k * NPIX + p0 + wp]);
    }
    __syncthreads();

    int p  = p0 + warpId;
    int b  = p / HWTOT;
    int c0 = lane * 8;

    const __half* xb = g_xt + (size_t)b * HWTOT * CH + c0;

    // Hoist w0 loads (independent of gathers).
    float4 wa = __ldg((const float4*)(w0 + c0));
    float4 wb = __ldg((const float4*)(w0 + c0 + 4));

    __half2 feat[4];
    __half2 ninf = __float2half2_rn(-65504.f);
#pragma unroll
    for (int j = 0; j < 4; j++) feat[j] = ninf;

#pragma unroll
    for (int k = 0; k < 9; k++) {
        uint4 m = smeta[warpId][k];               // broadcast LDS.128
        __half2 wA = *(const __half2*)&m.x;        // (w00, w01)
        __half2 wB = *(const __half2*)&m.y;        // (w10, w11)
        unsigned o00 = (m.z & 0xFFFFu) << 9, o01 = (m.z >> 16) << 9;
        unsigned o10 = (m.w & 0xFFFFu) << 9, o11 = (m.w >> 16) << 9;

        __half2 samp[4];
        corner8_mul(samp, xb, o00, __low2half2(wA));
        corner8(samp, xb, o01, __high2half2(wA));
        corner8(samp, xb, o10, __low2half2(wB));
        corner8(samp, xb, o11, __high2half2(wB));
#pragma unroll
        for (int j = 0; j < 4; j++) feat[j] = __hmax2(feat[j], samp[j]);
    }

    float2 f0 = __half22float2(feat[0]);
    float2 f1 = __half22float2(feat[1]);
    float2 f2 = __half22float2(feat[2]);
    float2 f3 = __half22float2(feat[3]);
    float acc = wa.x * f0.x + wa.y * f0.y + wa.z * f1.x + wa.w * f1.y
              + wb.x * f2.x + wb.y * f2.y + wb.z * f3.x + wb.w * f3.y;
#pragma unroll
    for (int s = 16; s > 0; s >>= 1)
        acc += __shfl_xor_sync(0xffffffffu, acc, s);
    if (lane == 0) {
        float v = acc + __ldg(b0);
        out[p] = 1.f / (1.f + expf(-v));
    }
}

// ---------------------------------------------------------------------------
extern "C" void kernel_launch(void* const* d_in, const int* in_sizes, int n_in,
                              void* d_out, int out_size)
{
    const float *x = nullptr, *offset = nullptr, *w0 = nullptr, *b0 = nullptr;
    for (int i = 0; i < n_in; i++) {
        if      (in_sizes[i] == BATCH * CH * HWTOT) x      = (const float*)d_in[i];
        else if (in_sizes[i] == BATCH * 18 * HWTOT) offset = (const float*)d_in[i];
        else if (in_sizes[i] == CH)                 w0     = (const float*)d_in[i];
        else if (in_sizes[i] == 1)                  b0     = (const float*)d_in[i];
    }

    prep<<<MGRID + TGRID, 256>>>(x, offset);

    dsa_main<<<NPIX / 8, 256>>>(w0, b0, (float*)d_out);
}